// round 13
// baseline (speedup 1.0000x reference)
#include <cuda_runtime.h>
#include <cstdint>

// Problem constants:
//   features: [B=4, C=256, H=64, W=64] fp32
//   rois:     [R=2048, 5] (batch, x1, y1, x2, y2), SPATIAL_SCALE = 0.25
//   Grid positions h=w={0,7,...,63} are EXACT integers -> bilinear == gather.
//   output:   [R, C, 9, 9] fp32  (maxpool 2x2 s1 of region-of-discard-masked 10x10)

#define BATCH 4
#define NCH   256
#define NPOS  100        // 10x10 grid per channel
#define CHB   128        // channels per block
#define NCHUNK (NCH / CHB)          // 2
#define THREADS 256      // 64 channel-PAIRS x 4 column-strips

// Transposed gather: G_t[b][pos][c] = features[b,c,7i,7j], channels contiguous.
__device__ float g_Gt[BATCH * NPOS * NCH];

__global__ void gather_grid_kernel(const float* __restrict__ feat) {
    int idx = blockIdx.x * blockDim.x + threadIdx.x;   // b*100*256 + p*256 + c
    if (idx >= BATCH * NPOS * NCH) return;
    int c  = idx % NCH;
    int bp = idx / NCH;
    int p  = bp % NPOS;
    int b  = bp / NPOS;
    int i = p / 10;
    int j = p % 10;
    g_Gt[idx] = feat[(((b * NCH + c) * 64) + i * 7) * 64 + j * 7];
}

// One column-strip of NCOLS grid columns -> NCOLS-1 output columns, for a
// PAIR of adjacent channels (float2 loads: one LDG.64 = 2 channels).
// Two 5-row phases, each front-batching 5*NCOLS LDG.64 (MLP~20), masking on
// the FMA pipe: mw[k] in {-1,0}, mh in {1,0}; v = fmaf(v, mh*mw, v)
//   -> inside: v - v = +0 exactly; outside: v unchanged.
// so points at channel 2*c2's 81-float row; channel 2*c2+1 is so+81.
template<int NCOLS>
__device__ __forceinline__ void strip(const float* __restrict__ gt,
                                      float* __restrict__ so,
                                      float x1, float x2, float y1, float y2,
                                      int c0)
{
    float mw[NCOLS];
    #pragma unroll
    for (int k = 0; k < NCOLS; k++) {
        float w = (float)(c0 + k) * 7.0f;
        mw[k] = ((w >= x1) && (w <= x2)) ? -1.0f : 0.0f;
    }

    float2 v[5][NCOLS];
    float2 hp[NCOLS - 1];

    // ---- Phase A: rows 0..4 -> output rows 0..3 ----
    #pragma unroll
    for (int i = 0; i < 5; i++)
        #pragma unroll
        for (int k = 0; k < NCOLS; k++)
            v[i][k] = __ldg((const float2*)(gt + (i * 10 + k) * NCH));

    #pragma unroll
    for (int i = 0; i < 5; i++) {
        float h = (float)i * 7.0f;
        float mh = ((h >= y1) && (h <= y2)) ? 1.0f : 0.0f;
        #pragma unroll
        for (int k = 0; k < NCOLS; k++) {
            float t = mh * mw[k];
            v[i][k].x = fmaf(v[i][k].x, t, v[i][k].x);
            v[i][k].y = fmaf(v[i][k].y, t, v[i][k].y);
        }
    }

    #pragma unroll
    for (int k = 0; k < NCOLS - 1; k++) {
        hp[k].x = fmaxf(v[0][k].x, v[0][k + 1].x);
        hp[k].y = fmaxf(v[0][k].y, v[0][k + 1].y);
    }
    #pragma unroll
    for (int i = 1; i < 5; i++) {
        float2 hc[NCOLS - 1];
        #pragma unroll
        for (int k = 0; k < NCOLS - 1; k++) {
            hc[k].x = fmaxf(v[i][k].x, v[i][k + 1].x);
            hc[k].y = fmaxf(v[i][k].y, v[i][k + 1].y);
        }
        #pragma unroll
        for (int k = 0; k < NCOLS - 1; k++) {
            so[(i - 1) * 9 + k]      = fmaxf(hp[k].x, hc[k].x);
            so[81 + (i - 1) * 9 + k] = fmaxf(hp[k].y, hc[k].y);
        }
        #pragma unroll
        for (int k = 0; k < NCOLS - 1; k++)
            hp[k] = hc[k];
    }

    // ---- Phase B: rows 5..9 -> output rows 4..8 (hp carries row 4) ----
    #pragma unroll
    for (int i = 0; i < 5; i++)
        #pragma unroll
        for (int k = 0; k < NCOLS; k++)
            v[i][k] = __ldg((const float2*)(gt + ((i + 5) * 10 + k) * NCH));

    #pragma unroll
    for (int i = 0; i < 5; i++) {
        float h = (float)(i + 5) * 7.0f;
        float mh = ((h >= y1) && (h <= y2)) ? 1.0f : 0.0f;
        #pragma unroll
        for (int k = 0; k < NCOLS; k++) {
            float t = mh * mw[k];
            v[i][k].x = fmaf(v[i][k].x, t, v[i][k].x);
            v[i][k].y = fmaf(v[i][k].y, t, v[i][k].y);
        }
    }

    #pragma unroll
    for (int i = 0; i < 5; i++) {
        float2 hc[NCOLS - 1];
        #pragma unroll
        for (int k = 0; k < NCOLS - 1; k++) {
            hc[k].x = fmaxf(v[i][k].x, v[i][k + 1].x);
            hc[k].y = fmaxf(v[i][k].y, v[i][k + 1].y);
        }
        #pragma unroll
        for (int k = 0; k < NCOLS - 1; k++) {
            so[(i + 4) * 9 + k]      = fmaxf(hp[k].x, hc[k].x);
            so[81 + (i + 4) * 9 + k] = fmaxf(hp[k].y, hc[k].y);
        }
        #pragma unroll
        for (int k = 0; k < NCOLS - 1; k++)
            hp[k] = hc[k];
    }
}

__global__ __launch_bounds__(THREADS, 4) void rod_align_max_kernel(
    const float* __restrict__ rois,
    float* __restrict__ out)
{
    __shared__ __align__(16) float sout[CHB * 81];   // 41472 B staged outputs

    const int r     = blockIdx.x;      // roi
    const int chunk = blockIdx.y;      // channel chunk (0..1)
    const int tid   = threadIdx.x;
    // 4 column-strips x 64 channel-pairs. Warps {0,1}->q0, {2,3}->q1, ...
    // Lanes within a warp = 32 consecutive channel pairs -> 256B coalesced.
    //   q=0: cols 0..3 -> j=0..2     q=1: cols 3..5 -> j=3..4
    //   q=2: cols 5..7 -> j=5..6     q=3: cols 7..9 -> j=7..8
    const int c2 = tid & 63;           // channel pair within chunk
    const int q  = tid >> 6;           // strip id

    const float x1 = rois[r * 5 + 1] * 0.25f;
    const float y1 = rois[r * 5 + 2] * 0.25f;
    const float x2 = rois[r * 5 + 3] * 0.25f;
    const float y2 = rois[r * 5 + 4] * 0.25f;
    const int   b  = (int)rois[r * 5 + 0];

    const float* gbase = g_Gt + b * (NPOS * NCH) + chunk * CHB + 2 * c2;
    float* so = sout + (2 * c2) * 81;

    if (q == 0)      strip<4>(gbase,           so,     x1, x2, y1, y2, 0);
    else if (q == 1) strip<3>(gbase + 3 * NCH, so + 3, x1, x2, y1, y2, 3);
    else if (q == 2) strip<3>(gbase + 5 * NCH, so + 5, x1, x2, y1, y2, 5);
    else             strip<3>(gbase + 7 * NCH, so + 7, x1, x2, y1, y2, 7);

    // Hand the 41472B contiguous staged block to TMA for the global write.
    asm volatile("fence.proxy.async.shared::cta;" ::: "memory");
    __syncthreads();
    if (tid == 0) {
        uint32_t saddr;
        asm("{ .reg .u64 t; cvta.to.shared.u64 t, %1; cvt.u32.u64 %0, t; }"
            : "=r"(saddr) : "l"(sout));
        float* gdst = out + (size_t)(r * NCH + chunk * CHB) * 81;
        asm volatile(
            "cp.async.bulk.global.shared::cta.bulk_group [%0], [%1], %2;"
            :: "l"(gdst), "r"(saddr), "r"((int)(CHB * 81 * 4)) : "memory");
        asm volatile("cp.async.bulk.commit_group;" ::: "memory");
        // Must not exit the CTA while TMA is still reading our smem.
        asm volatile("cp.async.bulk.wait_group.read 0;" ::: "memory");
    }
}

extern "C" void kernel_launch(void* const* d_in, const int* in_sizes, int n_in,
                              void* d_out, int out_size) {
    const float* features = (const float*)d_in[0];   // [4,256,64,64]
    const float* rois     = (const float*)d_in[1];   // [2048,5]
    float* out = (float*)d_out;                      // [2048,256,9,9]

    const int R = in_sizes[1] / 5;                   // 2048

    int n_g = BATCH * NPOS * NCH;
    gather_grid_kernel<<<(n_g + 255) / 256, 256>>>(features);

    dim3 grid(R, NCHUNK);
    rod_align_max_kernel<<<grid, THREADS>>>(rois, out);
}

// round 14
// speedup vs baseline: 1.1319x; 1.1319x over previous
#include <cuda_runtime.h>
#include <cstdint>

// Problem constants:
//   features: [B=4, C=256, H=64, W=64] fp32
//   rois:     [R=2048, 5] (batch, x1, y1, x2, y2), SPATIAL_SCALE = 0.25
//   Grid positions h=w={0,7,...,63} are EXACT integers -> bilinear == gather.
//   output:   [R, C, 9, 9] fp32  (maxpool 2x2 s1 of region-of-discard-masked 10x10)

#define BATCH 4
#define NCH   256
#define NPOS  100        // 10x10 grid per channel
#define CHB   64         // channels per block
#define NCHUNK (NCH / CHB)
#define THREADS 128      // 64 channels x 2 column-strips (6 cols / 5 cols)

// Transposed gather: G_t[b][pos][c] = features[b,c,7i,7j], channels contiguous.
__device__ float g_Gt[BATCH * NPOS * NCH];

__global__ void gather_grid_kernel(const float* __restrict__ feat) {
    int idx = blockIdx.x * blockDim.x + threadIdx.x;   // b*100*256 + p*256 + c
    if (idx >= BATCH * NPOS * NCH) return;
    int c  = idx % NCH;
    int bp = idx / NCH;
    int p  = bp % NPOS;
    int b  = bp / NPOS;
    int i = p / 10;
    int j = p % 10;
    g_Gt[idx] = feat[(((b * NCH + c) * 64) + i * 7) * 64 + j * 7];
}

// One column-strip of NCOLS grid columns -> NCOLS-1 output columns.
// Two 5-row phases; each front-batches 5*NCOLS unconditional scalar LDGs
// (MLP ~30, compile-time offsets), then masks on the FMA pipe:
//   mw[k] in {-1,0}, mh in {1,0}; v = fmaf(v, mh*mw, v)
//   -> inside: v - v = +0 exactly; outside: v unchanged.
template<int NCOLS>
__device__ __forceinline__ void strip(const float* __restrict__ gt,
                                      float* __restrict__ so,
                                      float x1, float x2, float y1, float y2,
                                      int c0)
{
    float mw[NCOLS];
    #pragma unroll
    for (int k = 0; k < NCOLS; k++) {
        float w = (float)(c0 + k) * 7.0f;
        mw[k] = ((w >= x1) && (w <= x2)) ? -1.0f : 0.0f;
    }

    float v[5][NCOLS];
    float hp[NCOLS - 1];

    // ---- Phase A: rows 0..4 -> output rows 0..3 ----
    #pragma unroll
    for (int i = 0; i < 5; i++)
        #pragma unroll
        for (int k = 0; k < NCOLS; k++)
            v[i][k] = __ldg(&gt[(i * 10 + k) * NCH]);

    #pragma unroll
    for (int i = 0; i < 5; i++) {
        float h = (float)i * 7.0f;
        float mh = ((h >= y1) && (h <= y2)) ? 1.0f : 0.0f;
        #pragma unroll
        for (int k = 0; k < NCOLS; k++)
            v[i][k] = fmaf(v[i][k], mh * mw[k], v[i][k]);
    }

    #pragma unroll
    for (int k = 0; k < NCOLS - 1; k++)
        hp[k] = fmaxf(v[0][k], v[0][k + 1]);
    #pragma unroll
    for (int i = 1; i < 5; i++) {
        float hc[NCOLS - 1];
        #pragma unroll
        for (int k = 0; k < NCOLS - 1; k++)
            hc[k] = fmaxf(v[i][k], v[i][k + 1]);
        #pragma unroll
        for (int k = 0; k < NCOLS - 1; k++)
            so[(i - 1) * 9 + k] = fmaxf(hp[k], hc[k]);
        #pragma unroll
        for (int k = 0; k < NCOLS - 1; k++)
            hp[k] = hc[k];
    }

    // ---- Phase B: rows 5..9 -> output rows 4..8 (hp carries row 4) ----
    #pragma unroll
    for (int i = 0; i < 5; i++)
        #pragma unroll
        for (int k = 0; k < NCOLS; k++)
            v[i][k] = __ldg(&gt[((i + 5) * 10 + k) * NCH]);

    #pragma unroll
    for (int i = 0; i < 5; i++) {
        float h = (float)(i + 5) * 7.0f;
        float mh = ((h >= y1) && (h <= y2)) ? 1.0f : 0.0f;
        #pragma unroll
        for (int k = 0; k < NCOLS; k++)
            v[i][k] = fmaf(v[i][k], mh * mw[k], v[i][k]);
    }

    #pragma unroll
    for (int i = 0; i < 5; i++) {
        float hc[NCOLS - 1];
        #pragma unroll
        for (int k = 0; k < NCOLS - 1; k++)
            hc[k] = fmaxf(v[i][k], v[i][k + 1]);
        #pragma unroll
        for (int k = 0; k < NCOLS - 1; k++)
            so[(i + 4) * 9 + k] = fmaxf(hp[k], hc[k]);
        #pragma unroll
        for (int k = 0; k < NCOLS - 1; k++)
            hp[k] = hc[k];
    }
}

__global__ __launch_bounds__(THREADS, 8) void rod_align_max_kernel(
    const float* __restrict__ rois,
    float* __restrict__ out)
{
    __shared__ __align__(16) float sout[CHB * 81];   // 20736 B staged outputs

    const int r     = blockIdx.x;      // roi
    const int chunk = blockIdx.y;      // channel chunk
    const int tid   = threadIdx.x;
    // 2 column-strips; within each strip, warps hold 32 consecutive channels.
    //   q=0 (warps 0-1): cols 0..5 -> j=0..4
    //   q=1 (warps 2-3): cols 5..9 -> j=5..8
    const int c = tid & (CHB - 1);     // channel within chunk
    const int q = tid >> 6;            // strip id

    const float x1 = rois[r * 5 + 1] * 0.25f;
    const float y1 = rois[r * 5 + 2] * 0.25f;
    const float x2 = rois[r * 5 + 3] * 0.25f;
    const float y2 = rois[r * 5 + 4] * 0.25f;
    const int   b  = (int)rois[r * 5 + 0];

    const float* gbase = g_Gt + b * (NPOS * NCH) + chunk * CHB + c;
    float* so = sout + c * 81;         // stride 81 (odd) -> conflict-free STS

    if (q == 0) strip<6>(gbase,           so,     x1, x2, y1, y2, 0);
    else        strip<5>(gbase + 5 * NCH, so + 5, x1, x2, y1, y2, 5);

    // Hand the 20736B contiguous staged block to TMA for the global write.
    asm volatile("fence.proxy.async.shared::cta;" ::: "memory");
    __syncthreads();
    if (tid == 0) {
        uint32_t saddr;
        asm("{ .reg .u64 t; cvta.to.shared.u64 t, %1; cvt.u32.u64 %0, t; }"
            : "=r"(saddr) : "l"(sout));
        float* gdst = out + (size_t)(r * NCH + chunk * CHB) * 81;
        asm volatile(
            "cp.async.bulk.global.shared::cta.bulk_group [%0], [%1], %2;"
            :: "l"(gdst), "r"(saddr), "r"((int)(CHB * 81 * 4)) : "memory");
        asm volatile("cp.async.bulk.commit_group;" ::: "memory");
        // Must not exit the CTA while TMA is still reading our smem.
        asm volatile("cp.async.bulk.wait_group.read 0;" ::: "memory");
    }
}

extern "C" void kernel_launch(void* const* d_in, const int* in_sizes, int n_in,
                              void* d_out, int out_size) {
    const float* features = (const float*)d_in[0];   // [4,256,64,64]
    const float* rois     = (const float*)d_in[1];   // [2048,5]
    float* out = (float*)d_out;                      // [2048,256,9,9]

    const int R = in_sizes[1] / 5;                   // 2048

    int n_g = BATCH * NPOS * NCH;
    gather_grid_kernel<<<(n_g + 255) / 256, 256>>>(features);

    dim3 grid(R, NCHUNK);
    rod_align_max_kernel<<<grid, THREADS>>>(rois, out);
}